// round 8
// baseline (speedup 1.0000x reference)
#include <cuda_runtime.h>
#include <math.h>

// Problem constants
#define BB 32
#define TT 1000
#define DD 640
#define VV 1024
#define NB 128   // CTAs (<= 148 SMs -> all co-resident, safe for sw grid barrier)
#define NT 256   // threads per CTA (8 warps)

// ---------------- persistent device state (no allocations allowed) ----------
__device__ __align__(16) float g_hbuf[2][BB][DD];   // double-buffered h
__device__ __align__(16) float g_c[BB][DD];
__device__ __align__(16) float g_out_pn[BB][DD];
__device__ __align__(16) float g_z[BB][DD];
__device__ __align__(16) float g_logits[BB][VV];
__device__ int   g_tok[BB];
__device__ float g_score[BB];
__device__ int   g_nonblank[BB];
__device__ unsigned long long g_bar = 0ull;         // monotone barrier counter

// ---------------- grid barrier (counting, no reset; counter ends on a
// multiple of NB each launch so graph replays stay consistent) --------------
__device__ __forceinline__ void grid_barrier() {
    __syncthreads();
    if (threadIdx.x == 0) {
        __threadfence();
        unsigned long long m = atomicAdd(&g_bar, 1ull) + 1ull;
        unsigned long long goal = ((m + (unsigned long long)NB - 1ull) /
                                   (unsigned long long)NB) * (unsigned long long)NB;
        while (*((volatile unsigned long long*)&g_bar) < goal) { }
        __threadfence();
    }
    __syncthreads();
}

__device__ __forceinline__ float wred(float v) {
    v += __shfl_xor_sync(0xffffffffu, v, 16);
    v += __shfl_xor_sync(0xffffffffu, v, 8);
    v += __shfl_xor_sync(0xffffffffu, v, 4);
    v += __shfl_xor_sync(0xffffffffu, v, 2);
    v += __shfl_xor_sync(0xffffffffu, v, 1);
    return v;
}

__device__ __forceinline__ float sigf(float x) { return 1.0f / (1.0f + expf(-x)); }

// ============================================================================
// Phase Z: z[b][j] = tanh( tn[b][t]·W_tn[j] + out_pn[b]·W_pn[j] + b_joint[j] )
// CTA owns 5 j-columns; warp owns 4 batches; lanes split K with float4.
// ============================================================================
__device__ __forceinline__ void z_phase(
    int cc, int lane, int b0, int t,
    const float* __restrict__ tn, const float* __restrict__ W_tn,
    const float* __restrict__ W_pn, const float* __restrict__ b_joint)
{
    const int j0 = cc * 5;
    float acc[4][5];
#pragma unroll
    for (int i = 0; i < 4; i++)
#pragma unroll
        for (int j = 0; j < 5; j++) acc[i][j] = 0.f;

    for (int kc = 0; kc < DD; kc += 128) {
        const int k = kc + lane * 4;
        float4 a1[4], a2[4];
#pragma unroll
        for (int i = 0; i < 4; i++) {
            a1[i] = *(const float4*)(tn + ((size_t)(b0 + i) * TT + (size_t)t) * DD + k);
            a2[i] = *(const float4*)(&g_out_pn[b0 + i][k]);
        }
#pragma unroll
        for (int j = 0; j < 5; j++) {
            float4 w1 = *(const float4*)(W_tn + (size_t)(j0 + j) * DD + k);
            float4 w2 = *(const float4*)(W_pn + (size_t)(j0 + j) * DD + k);
#pragma unroll
            for (int i = 0; i < 4; i++) {
                float a = acc[i][j];
                a = fmaf(a1[i].x, w1.x, a); a = fmaf(a1[i].y, w1.y, a);
                a = fmaf(a1[i].z, w1.z, a); a = fmaf(a1[i].w, w1.w, a);
                a = fmaf(a2[i].x, w2.x, a); a = fmaf(a2[i].y, w2.y, a);
                a = fmaf(a2[i].z, w2.z, a); a = fmaf(a2[i].w, w2.w, a);
                acc[i][j] = a;
            }
        }
    }
#pragma unroll
    for (int i = 0; i < 4; i++)
#pragma unroll
        for (int j = 0; j < 5; j++) acc[i][j] = wred(acc[i][j]);

    if (lane == 0) {
#pragma unroll
        for (int i = 0; i < 4; i++)
#pragma unroll
            for (int j = 0; j < 5; j++)
                g_z[b0 + i][j0 + j] = tanhf(acc[i][j] + b_joint[j0 + j]);
    }
}

// ============================================================================
// Phase L: logits[b][v] = z[b]·W_out[v] + b_out[v].  CTA owns 8 v-columns.
// ============================================================================
__device__ __forceinline__ void logits_phase(
    int cc, int lane, int b0,
    const float* __restrict__ W_out, const float* __restrict__ b_out)
{
    const int v0 = cc * 8;
    float acc[4][8];
#pragma unroll
    for (int i = 0; i < 4; i++)
#pragma unroll
        for (int v = 0; v < 8; v++) acc[i][v] = 0.f;

    for (int kc = 0; kc < DD; kc += 128) {
        const int k = kc + lane * 4;
        float4 zv[4];
#pragma unroll
        for (int i = 0; i < 4; i++) zv[i] = *(const float4*)(&g_z[b0 + i][k]);
#pragma unroll
        for (int v = 0; v < 8; v++) {
            float4 wv = *(const float4*)(W_out + (size_t)(v0 + v) * DD + k);
#pragma unroll
            for (int i = 0; i < 4; i++) {
                float a = acc[i][v];
                a = fmaf(zv[i].x, wv.x, a); a = fmaf(zv[i].y, wv.y, a);
                a = fmaf(zv[i].z, wv.z, a); a = fmaf(zv[i].w, wv.w, a);
                acc[i][v] = a;
            }
        }
    }
#pragma unroll
    for (int i = 0; i < 4; i++)
#pragma unroll
        for (int v = 0; v < 8; v++) acc[i][v] = wred(acc[i][v]);

    if (lane == 0) {
#pragma unroll
        for (int i = 0; i < 4; i++)
#pragma unroll
            for (int v = 0; v < 8; v++)
                g_logits[b0 + i][v0 + v] = acc[i][v] + b_out[v0 + v];
    }
}

// ============================================================================
// Phase R: CTA b (< 32) does argmax (first-index on tie) + logsumexp + state.
// ============================================================================
__device__ __forceinline__ void reduce_phase(int cc, int tid, int t,
                                             float* __restrict__ out)
{
    if (cc >= BB) return;  // whole CTA returns together; __syncthreads safe below
    const int b = cc;
    __shared__ float sl[VV];
    __shared__ float smax[NT];
    __shared__ int   sidx[NT];
    __shared__ float ssum[NT];

    for (int v = tid; v < VV; v += NT) sl[v] = g_logits[b][v];
    __syncthreads();

    float mx = -3.4e38f; int mi = 0;
    for (int v = tid; v < VV; v += NT) {
        float x = sl[v];
        if (x > mx) { mx = x; mi = v; }   // strict > keeps lowest index in-thread
    }
    smax[tid] = mx; sidx[tid] = mi;
    __syncthreads();
    for (int s = NT / 2; s > 0; s >>= 1) {
        if (tid < s) {
            float om = smax[tid + s]; int oi = sidx[tid + s];
            if (om > smax[tid] || (om == smax[tid] && oi < sidx[tid])) {
                smax[tid] = om; sidx[tid] = oi;
            }
        }
        __syncthreads();
    }
    mx = smax[0]; mi = sidx[0];

    float ss = 0.f;
    for (int v = tid; v < VV; v += NT) ss += expf(sl[v] - mx);
    ssum[tid] = ss;
    __syncthreads();
    for (int s = NT / 2; s > 0; s >>= 1) {
        if (tid < s) ssum[tid] += ssum[tid + s];
        __syncthreads();
    }

    if (tid == 0) {
        float lp = -logf(ssum[0]);            // logp at argmax
        int nb = (mi != 0);
        if (nb) { g_score[b] += lp; g_tok[b] = mi; }
        g_nonblank[b] = nb;
        out[(size_t)b * TT + t] = nb ? (float)mi : 0.0f;
    }
}

// ============================================================================
// Phase G: gates[b][g] = E[tok[b]]·W_ih[g] + h[b]·W_hh[g] + b_lstm[g],
// then LSTM update of CTA-owned 5 j-columns (i/f/g/o co-located => no extra
// sync). Reads h from buffer rp, writes buffer rp^1 (avoids read/write race).
// ============================================================================
__device__ __forceinline__ void gates_phase(
    int cc, int lane, int b0,
    const float* __restrict__ E, const float* __restrict__ W_ih,
    const float* __restrict__ W_hh, const float* __restrict__ b_lstm, int rp)
{
    const int j0 = cc * 5;
    float acc[4][20];
#pragma unroll
    for (int i = 0; i < 4; i++)
#pragma unroll
        for (int o = 0; o < 20; o++) acc[i][o] = 0.f;

    const float* xp[4];
#pragma unroll
    for (int i = 0; i < 4; i++) xp[i] = E + (size_t)g_tok[b0 + i] * DD;

    for (int kc = 0; kc < DD; kc += 128) {
        const int k = kc + lane * 4;
        float4 xv[4], hv[4];
#pragma unroll
        for (int i = 0; i < 4; i++) {
            xv[i] = *(const float4*)(xp[i] + k);
            hv[i] = *(const float4*)(&g_hbuf[rp][b0 + i][k]);
        }
#pragma unroll
        for (int o = 0; o < 20; o++) {
            const int row = (o / 5) * DD + j0 + (o % 5);
            float4 wi = *(const float4*)(W_ih + (size_t)row * DD + k);
            float4 wh = *(const float4*)(W_hh + (size_t)row * DD + k);
#pragma unroll
            for (int i = 0; i < 4; i++) {
                float a = acc[i][o];
                a = fmaf(xv[i].x, wi.x, a); a = fmaf(xv[i].y, wi.y, a);
                a = fmaf(xv[i].z, wi.z, a); a = fmaf(xv[i].w, wi.w, a);
                a = fmaf(hv[i].x, wh.x, a); a = fmaf(hv[i].y, wh.y, a);
                a = fmaf(hv[i].z, wh.z, a); a = fmaf(hv[i].w, wh.w, a);
                acc[i][o] = a;
            }
        }
    }
#pragma unroll
    for (int i = 0; i < 4; i++)
#pragma unroll
        for (int o = 0; o < 20; o++) acc[i][o] = wred(acc[i][o]);

    if (lane == 0) {
#pragma unroll
        for (int i = 0; i < 4; i++) {
            const int b = b0 + i;
            const int nb = g_nonblank[b];
#pragma unroll
            for (int jj = 0; jj < 5; jj++) {
                const int j = j0 + jj;
                if (nb) {
                    float gi = acc[i][jj]      + b_lstm[j];
                    float gf = acc[i][5 + jj]  + b_lstm[DD + j];
                    float gg = acc[i][10 + jj] + b_lstm[2 * DD + j];
                    float go = acc[i][15 + jj] + b_lstm[3 * DD + j];
                    float cn = sigf(gf) * g_c[b][j] + sigf(gi) * tanhf(gg);
                    float hn = sigf(go) * tanhf(cn);
                    g_c[b][j] = cn;
                    g_hbuf[rp ^ 1][b][j] = hn;
                    g_out_pn[b][j] = hn;
                } else {
                    g_hbuf[rp ^ 1][b][j] = g_hbuf[rp][b][j];
                }
            }
        }
    }
}

// ============================================================================
// Persistent kernel: init -> prime LSTM -> 1000 x {Z | L | R | G}
// ============================================================================
__global__ void __launch_bounds__(NT, 1)
rnnt_decode_kernel(const float* __restrict__ tn,     const float* __restrict__ E,
                   const float* __restrict__ W_ih,   const float* __restrict__ W_hh,
                   const float* __restrict__ b_lstm, const float* __restrict__ W_tn,
                   const float* __restrict__ W_pn,   const float* __restrict__ b_joint,
                   const float* __restrict__ W_out,  const float* __restrict__ b_out,
                   float* __restrict__ out)
{
    const int cc   = blockIdx.x;
    const int tid  = threadIdx.x;
    const int lane = tid & 31;
    const int b0   = (tid >> 5) * 4;   // warp -> 4 batches

    // ---- per-launch state init (deterministic across graph replays) ----
    for (int i = cc * NT + tid; i < BB * DD; i += NB * NT) {
        (&g_hbuf[0][0][0])[i] = 0.f;
        (&g_c[0][0])[i]       = 0.f;
    }
    if (cc == 0 && tid < BB) {
        g_tok[tid] = 0;            // BLANK
        g_score[tid] = 0.f;
        g_nonblank[tid] = 1;       // force priming LSTM update to apply
    }
    grid_barrier();

    // ---- priming LSTM step: h,c = lstm(E[BLANK], 0, 0); out_pn = h ----
    int par = 0;
    gates_phase(cc, lane, b0, E, W_ih, W_hh, b_lstm, par);
    par ^= 1;
    grid_barrier();

    // ---- sequential decode ----
    for (int t = 0; t < TT; t++) {
        z_phase(cc, lane, b0, t, tn, W_tn, W_pn, b_joint);
        grid_barrier();
        logits_phase(cc, lane, b0, W_out, b_out);
        grid_barrier();
        reduce_phase(cc, tid, t, out);
        grid_barrier();
        if (t < TT - 1) {          // final step's LSTM never affects outputs
            gates_phase(cc, lane, b0, E, W_ih, W_hh, b_lstm, par);
            par ^= 1;
            grid_barrier();
        }
    }

    // ---- epilogue: scores + mean(exp(score)) ----
    if (cc == 0) {
        if (tid < BB) out[(size_t)BB * TT + tid] = g_score[tid];
        if (tid == 0) {
            float s = 0.f;
            for (int b = 0; b < BB; b++) s += expf(g_score[b]);
            out[(size_t)BB * TT + BB] = s / (float)BB;
        }
    }
}

extern "C" void kernel_launch(void* const* d_in, const int* in_sizes, int n_in,
                              void* d_out, int out_size)
{
    (void)in_sizes; (void)n_in; (void)out_size;
    const float* tn      = (const float*)d_in[0];
    const float* E       = (const float*)d_in[1];
    const float* W_ih    = (const float*)d_in[2];
    const float* W_hh    = (const float*)d_in[3];
    const float* b_lstm  = (const float*)d_in[4];
    const float* W_tn    = (const float*)d_in[5];
    const float* W_pn    = (const float*)d_in[6];
    const float* b_joint = (const float*)d_in[7];
    const float* W_out   = (const float*)d_in[8];
    const float* b_out   = (const float*)d_in[9];
    float* out = (float*)d_out;

    rnnt_decode_kernel<<<NB, NT>>>(tn, E, W_ih, W_hh, b_lstm,
                                   W_tn, W_pn, b_joint, W_out, b_out, out);
}

// round 9
// speedup vs baseline: 1.4103x; 1.4103x over previous
#include <cuda_runtime.h>
#include <math.h>

// Problem constants
#define BB 32
#define TT 1000
#define DD 640
#define VV 1024
#define NB 128   // CTAs (<= 148 SMs -> all co-resident, safe for sw grid barrier)
#define NT 512   // 16 warps per CTA (HW caps regs at 128/thread -> no 255-reg spills)

// ---------------- persistent device state (no allocations allowed) ----------
__device__ __align__(16) float g_hbuf[2][BB][DD];   // double-buffered h
__device__ __align__(16) float g_c[BB][DD];
__device__ __align__(16) float g_out_pn[BB][DD];
__device__ __align__(16) float g_z[BB][DD];
__device__ __align__(16) float4 g_part[BB][NB];     // (max, sumexp, argmax, -) per CTA
__device__ float g_score[BB];
__device__ unsigned long long g_bar = 0ull;         // monotone barrier counter

// ---------------- grid barrier (counting, no reset; deterministic count per
// launch so graph replays stay consistent) ----------------------------------
__device__ __forceinline__ void grid_barrier() {
    __syncthreads();
    if (threadIdx.x == 0) {
        __threadfence();
        unsigned long long m = atomicAdd(&g_bar, 1ull) + 1ull;
        unsigned long long goal = ((m + (unsigned long long)NB - 1ull) /
                                   (unsigned long long)NB) * (unsigned long long)NB;
        while (*((volatile unsigned long long*)&g_bar) < goal) { }
        __threadfence();
    }
    __syncthreads();
}

__device__ __forceinline__ float wred(float v) {
    v += __shfl_xor_sync(0xffffffffu, v, 16);
    v += __shfl_xor_sync(0xffffffffu, v, 8);
    v += __shfl_xor_sync(0xffffffffu, v, 4);
    v += __shfl_xor_sync(0xffffffffu, v, 2);
    v += __shfl_xor_sync(0xffffffffu, v, 1);
    return v;
}

__device__ __forceinline__ float sigf(float x) { return 1.0f / (1.0f + expf(-x)); }

// Order-independent logsumexp/argmax merge (first-index on exact ties).
__device__ __forceinline__ void pmerge(float& m, float& s, int& mi,
                                       float m2, float s2, int i2) {
    if (m2 > m || (m2 == m && i2 < mi)) {
        s = s2 + s * expf(m - m2);
        m = m2; mi = i2;
    } else {
        s = s + s2 * expf(m2 - m);
    }
}

// ============================================================================
// Phase Z: z[b][j] = tanh( tn[b][t]·W_tn[j] + out_pn[b]·W_pn[j] + b_joint[j] )
// 16 warps: warp owns 2 batches; CTA owns 5 j-columns; lanes split K (float4).
// ============================================================================
__device__ __forceinline__ void z_phase(
    int cc, int wid, int lane, int t,
    const float* __restrict__ tn, const float* __restrict__ W_tn,
    const float* __restrict__ W_pn, const float* __restrict__ b_joint)
{
    const int j0 = cc * 5;
    const int b0 = wid * 2;
    float acc[2][5];
#pragma unroll
    for (int i = 0; i < 2; i++)
#pragma unroll
        for (int j = 0; j < 5; j++) acc[i][j] = 0.f;

    for (int kc = 0; kc < DD; kc += 128) {
        const int k = kc + lane * 4;
        float4 a1[2], a2[2];
#pragma unroll
        for (int i = 0; i < 2; i++) {
            a1[i] = *(const float4*)(tn + ((size_t)(b0 + i) * TT + (size_t)t) * DD + k);
            a2[i] = *(const float4*)(&g_out_pn[b0 + i][k]);
        }
#pragma unroll
        for (int j = 0; j < 5; j++) {
            float4 w1 = *(const float4*)(W_tn + (size_t)(j0 + j) * DD + k);
            float4 w2 = *(const float4*)(W_pn + (size_t)(j0 + j) * DD + k);
#pragma unroll
            for (int i = 0; i < 2; i++) {
                float a = acc[i][j];
                a = fmaf(a1[i].x, w1.x, a); a = fmaf(a1[i].y, w1.y, a);
                a = fmaf(a1[i].z, w1.z, a); a = fmaf(a1[i].w, w1.w, a);
                a = fmaf(a2[i].x, w2.x, a); a = fmaf(a2[i].y, w2.y, a);
                a = fmaf(a2[i].z, w2.z, a); a = fmaf(a2[i].w, w2.w, a);
                acc[i][j] = a;
            }
        }
    }
#pragma unroll
    for (int i = 0; i < 2; i++)
#pragma unroll
        for (int j = 0; j < 5; j++) acc[i][j] = wred(acc[i][j]);

    if (lane == 0) {
#pragma unroll
        for (int i = 0; i < 2; i++)
#pragma unroll
            for (int j = 0; j < 5; j++)
                g_z[b0 + i][j0 + j] = tanhf(acc[i][j] + b_joint[j0 + j]);
    }
}

// ============================================================================
// Phase L: logits for CTA's 8 v-columns; emit (max, sumexp, argmax) partial
// per (batch, CTA) instead of materializing logits. Warp owns 2 batches.
// ============================================================================
__device__ __forceinline__ void l_phase(
    int cc, int wid, int lane,
    const float* __restrict__ W_out, const float* __restrict__ b_out)
{
    const int v0 = cc * 8;
    const int b0 = wid * 2;
    float acc[2][8];
#pragma unroll
    for (int i = 0; i < 2; i++)
#pragma unroll
        for (int v = 0; v < 8; v++) acc[i][v] = 0.f;

    for (int kc = 0; kc < DD; kc += 128) {
        const int k = kc + lane * 4;
        float4 zv[2];
#pragma unroll
        for (int i = 0; i < 2; i++) zv[i] = *(const float4*)(&g_z[b0 + i][k]);
#pragma unroll
        for (int v = 0; v < 8; v++) {
            float4 wv = *(const float4*)(W_out + (size_t)(v0 + v) * DD + k);
#pragma unroll
            for (int i = 0; i < 2; i++) {
                float a = acc[i][v];
                a = fmaf(zv[i].x, wv.x, a); a = fmaf(zv[i].y, wv.y, a);
                a = fmaf(zv[i].z, wv.z, a); a = fmaf(zv[i].w, wv.w, a);
                acc[i][v] = a;
            }
        }
    }
#pragma unroll
    for (int i = 0; i < 2; i++)
#pragma unroll
        for (int v = 0; v < 8; v++) acc[i][v] = wred(acc[i][v]);

    if (lane == 0) {
#pragma unroll
        for (int i = 0; i < 2; i++) {
            float vals[8];
#pragma unroll
            for (int v = 0; v < 8; v++) vals[v] = acc[i][v] + b_out[v0 + v];
            float m = vals[0]; int mi = v0;
#pragma unroll
            for (int v = 1; v < 8; v++)
                if (vals[v] > m) { m = vals[v]; mi = v0 + v; }  // lowest idx on tie
            float s = 0.f;
#pragma unroll
            for (int v = 0; v < 8; v++) s += expf(vals[v] - m);
            g_part[b0 + i][cc] = make_float4(m, s, (float)mi, 0.f);
        }
    }
}

// ============================================================================
// Phase CG: (a) every CTA redundantly merges the 128 partials per batch
// (bitwise-deterministic) -> smem tok/nonblank; CTA 0 writes tokens + score.
// (b) LSTM gates GEMV: warps 0-7 gates {i,f}, warps 8-15 gates {g,o}, each
// warp 4 batches x 10 rows (acc=40 regs, no spills); pointwise via smem.
// ============================================================================
__device__ __forceinline__ void cg_phase(
    int cc, int wid, int lane, int t, int rp, int prime, int do_lstm,
    const float* __restrict__ E, const float* __restrict__ W_ih,
    const float* __restrict__ W_hh, const float* __restrict__ b_lstm,
    float* __restrict__ out, float* sg, int* s_tok, int* s_nb)
{
    if (!prime) {
        // warp wid merges partials for batches 2*wid, 2*wid+1
#pragma unroll
        for (int bi = 0; bi < 2; bi++) {
            const int b = wid * 2 + bi;
            float4 q = g_part[b][lane];
            float m = q.x, s = q.y; int mi = (int)q.z;
#pragma unroll
            for (int r = 1; r < 4; r++) {
                float4 p = g_part[b][lane + 32 * r];
                pmerge(m, s, mi, p.x, p.y, (int)p.z);
            }
#pragma unroll
            for (int d = 16; d > 0; d >>= 1) {
                float m2 = __shfl_xor_sync(0xffffffffu, m, d);
                float s2 = __shfl_xor_sync(0xffffffffu, s, d);
                int   i2 = __shfl_xor_sync(0xffffffffu, mi, d);
                pmerge(m, s, mi, m2, s2, i2);
            }
            if (lane == 0) {
                const int nb = (mi != 0);
                s_nb[b] = nb;
                s_tok[b] = nb ? mi : 0;   // blank-step LSTM result is discarded
                if (cc == 0) {
                    out[(size_t)b * TT + t] = nb ? (float)mi : 0.0f;
                    if (nb) g_score[b] += -logf(s);  // logp at argmax
                }
            }
        }
    } else {
        if (wid == 0) { s_tok[lane] = 0; s_nb[lane] = 1; }
    }
    __syncthreads();
    if (!do_lstm) return;

    const int j0 = cc * 5;
    const int pass = wid >> 3;          // 0: gates i,f   1: gates g,o
    const int b0 = (wid & 7) * 4;
    float acc[4][10];
#pragma unroll
    for (int i = 0; i < 4; i++)
#pragma unroll
        for (int o = 0; o < 10; o++) acc[i][o] = 0.f;

    const float* xp[4];
#pragma unroll
    for (int i = 0; i < 4; i++) xp[i] = E + (size_t)s_tok[b0 + i] * DD;

#pragma unroll 1
    for (int kc = 0; kc < DD; kc += 128) {
        const int k = kc + lane * 4;
        float4 xv[4], hv[4];
#pragma unroll
        for (int i = 0; i < 4; i++) {
            xv[i] = *(const float4*)(xp[i] + k);
            hv[i] = *(const float4*)(&g_hbuf[rp][b0 + i][k]);
        }
#pragma unroll
        for (int o = 0; o < 10; o++) {
            const int row = (pass * 2 + o / 5) * DD + j0 + (o % 5);
            float4 wi = *(const float4*)(W_ih + (size_t)row * DD + k);
            float4 wh = *(const float4*)(W_hh + (size_t)row * DD + k);
#pragma unroll
            for (int i = 0; i < 4; i++) {
                float a = acc[i][o];
                a = fmaf(xv[i].x, wi.x, a); a = fmaf(xv[i].y, wi.y, a);
                a = fmaf(xv[i].z, wi.z, a); a = fmaf(xv[i].w, wi.w, a);
                a = fmaf(hv[i].x, wh.x, a); a = fmaf(hv[i].y, wh.y, a);
                a = fmaf(hv[i].z, wh.z, a); a = fmaf(hv[i].w, wh.w, a);
                acc[i][o] = a;
            }
        }
    }
#pragma unroll
    for (int i = 0; i < 4; i++)
#pragma unroll
        for (int o = 0; o < 10; o++) acc[i][o] = wred(acc[i][o]);

    if (lane == 0) {
#pragma unroll
        for (int i = 0; i < 4; i++)
#pragma unroll
            for (int o = 0; o < 10; o++)
                sg[(b0 + i) * 20 + pass * 10 + o] = acc[i][o];
    }
    __syncthreads();

    // pointwise LSTM update: warps 0-7, lanes 0-19 -> (batch, j) pairs
    if (wid < 8 && lane < 20) {
        const int i = lane / 5, jj = lane - i * 5;
        const int b = wid * 4 + i;
        const int j = j0 + jj;
        if (s_nb[b]) {
            float gi = sg[b * 20 + jj]      + b_lstm[j];
            float gf = sg[b * 20 + 5 + jj]  + b_lstm[DD + j];
            float gg = sg[b * 20 + 10 + jj] + b_lstm[2 * DD + j];
            float go = sg[b * 20 + 15 + jj] + b_lstm[3 * DD + j];
            float cn = sigf(gf) * g_c[b][j] + sigf(gi) * tanhf(gg);
            float hn = sigf(go) * tanhf(cn);
            g_c[b][j] = cn;
            g_hbuf[rp ^ 1][b][j] = hn;
            g_out_pn[b][j] = hn;
        } else {
            g_hbuf[rp ^ 1][b][j] = g_hbuf[rp][b][j];
        }
    }
}

// ============================================================================
// Persistent kernel: init -> prime LSTM -> 1000 x {Z | L | CG} (3 barriers/step)
// ============================================================================
__global__ void __launch_bounds__(NT, 1)
rnnt_decode_kernel(const float* __restrict__ tn,     const float* __restrict__ E,
                   const float* __restrict__ W_ih,   const float* __restrict__ W_hh,
                   const float* __restrict__ b_lstm, const float* __restrict__ W_tn,
                   const float* __restrict__ W_pn,   const float* __restrict__ b_joint,
                   const float* __restrict__ W_out,  const float* __restrict__ b_out,
                   float* __restrict__ out)
{
    __shared__ float sg[BB * 20];
    __shared__ int   s_tok[BB];
    __shared__ int   s_nb[BB];

    const int cc   = blockIdx.x;
    const int tid  = threadIdx.x;
    const int lane = tid & 31;
    const int wid  = tid >> 5;

    // ---- per-launch state init (deterministic across graph replays) ----
    for (int i = cc * NT + tid; i < BB * DD; i += NB * NT) {
        (&g_hbuf[0][0][0])[i] = 0.f;
        (&g_c[0][0])[i]       = 0.f;
    }
    if (cc == 0 && tid < BB) g_score[tid] = 0.f;
    grid_barrier();

    // ---- priming LSTM step: h,c = lstm(E[BLANK], 0, 0); out_pn = h ----
    int par = 0;
    cg_phase(cc, wid, lane, 0, par, /*prime=*/1, /*do_lstm=*/1,
             E, W_ih, W_hh, b_lstm, out, sg, s_tok, s_nb);
    par ^= 1;
    grid_barrier();

    // ---- sequential decode ----
    for (int t = 0; t < TT; t++) {
        z_phase(cc, wid, lane, t, tn, W_tn, W_pn, b_joint);
        grid_barrier();
        l_phase(cc, wid, lane, W_out, b_out);
        grid_barrier();
        cg_phase(cc, wid, lane, t, par, /*prime=*/0,
                 /*do_lstm=*/(t < TT - 1) ? 1 : 0,
                 E, W_ih, W_hh, b_lstm, out, sg, s_tok, s_nb);
        if (t < TT - 1) { par ^= 1; grid_barrier(); }
    }

    // ---- epilogue: scores + mean(exp(score)) (CTA 0 owns g_score) ----
    __syncthreads();
    if (cc == 0) {
        if (tid < BB) out[(size_t)BB * TT + tid] = g_score[tid];
        if (tid == 0) {
            float s = 0.f;
            for (int b = 0; b < BB; b++) s += expf(g_score[b]);
            out[(size_t)BB * TT + BB] = s / (float)BB;
        }
    }
}

extern "C" void kernel_launch(void* const* d_in, const int* in_sizes, int n_in,
                              void* d_out, int out_size)
{
    (void)in_sizes; (void)n_in; (void)out_size;
    const float* tn      = (const float*)d_in[0];
    const float* E       = (const float*)d_in[1];
    const float* W_ih    = (const float*)d_in[2];
    const float* W_hh    = (const float*)d_in[3];
    const float* b_lstm  = (const float*)d_in[4];
    const float* W_tn    = (const float*)d_in[5];
    const float* W_pn    = (const float*)d_in[6];
    const float* b_joint = (const float*)d_in[7];
    const float* W_out   = (const float*)d_in[8];
    const float* b_out   = (const float*)d_in[9];
    float* out = (float*)d_out;

    rnnt_decode_kernel<<<NB, NT>>>(tn, E, W_ih, W_hh, b_lstm,
                                   W_tn, W_pn, b_joint, W_out, b_out, out);
}